// round 5
// baseline (speedup 1.0000x reference)
#include <cuda_runtime.h>

#define TT 12
#define NN 192
#define KK 24                       // final rank = 2*TT
#define NPAIRS 256
#define NROWS (TT * NPAIRS)         // 3072

// device scratch (static __device__ arrays are allowed; no dynamic allocs)
__device__ float g_H0T[NN * NN];
__device__ float g_G1[NROWS * NN];
__device__ float g_G2[NROWS * NN];
__device__ float g_U[NPAIRS * KK * NN];
__device__ float g_V[NPAIRS * KK * NN];

// ---------------------------------------------------------------------------
// Kernel 0: H0T = H0^T (tiled transpose)
// ---------------------------------------------------------------------------
__global__ void k_transpose(const float* __restrict__ H0)
{
    __shared__ float tbuf[32][33];
    const int bx = blockIdx.x % 6, by = blockIdx.x / 6;
    const int tx = threadIdx.x;
    for (int j = threadIdx.y; j < 32; j += 8)
        tbuf[j][tx] = H0[(by * 32 + j) * NN + bx * 32 + tx];
    __syncthreads();
    for (int j = threadIdx.y; j < 32; j += 8)
        g_H0T[(bx * 32 + j) * NN + by * 32 + tx] = tbuf[tx][j];
}

// ---------------------------------------------------------------------------
// Kernel A: batched GEMV as GEMM.
//   blockIdx.y==0: G1[r][i] = sum_k Y[r][k] * H0T[k][i]
//   blockIdx.y==1: G2[r][j] = sum_k Y[r][k] * H0 [k][j]
// CTA: 32 r-rows x 192 cols, 384 threads, 4x4 register tiles.
// ---------------------------------------------------------------------------
__global__ void __launch_bounds__(384)
k_gemm(const float* __restrict__ Y, const float* __restrict__ H0)
{
    __shared__ float Ysh[32][196];
    const int tid = threadIdx.x;
    const int r0 = blockIdx.x * 32;
    const float* __restrict__ Bm = blockIdx.y ? H0 : (const float*)g_H0T;
    float* __restrict__ Om = blockIdx.y ? g_G2 : g_G1;

    for (int idx = tid; idx < 32 * NN; idx += 384) {
        const int r = idx / NN, n = idx - r * NN;
        Ysh[r][n] = Y[(size_t)(r0 + r) * NN + n];
    }
    __syncthreads();

    const int cg = tid % 48;        // cols 4*cg .. 4*cg+3
    const int rg = tid / 48;        // rows 4*rg .. 4*rg+3
    float4 acc[4];
    #pragma unroll
    for (int rr = 0; rr < 4; rr++) acc[rr] = make_float4(0.f, 0.f, 0.f, 0.f);

    #pragma unroll 2
    for (int k4 = 0; k4 < NN / 4; k4++) {
        float4 hv[4];
        #pragma unroll
        for (int kk = 0; kk < 4; kk++)
            hv[kk] = *(const float4*)&Bm[(4 * k4 + kk) * NN + 4 * cg];
        #pragma unroll
        for (int rr = 0; rr < 4; rr++) {
            const float4 yv = *(const float4*)&Ysh[4 * rg + rr][4 * k4];
            acc[rr].x += yv.x * hv[0].x + yv.y * hv[1].x + yv.z * hv[2].x + yv.w * hv[3].x;
            acc[rr].y += yv.x * hv[0].y + yv.y * hv[1].y + yv.z * hv[2].y + yv.w * hv[3].y;
            acc[rr].z += yv.x * hv[0].z + yv.y * hv[1].z + yv.z * hv[2].z + yv.w * hv[3].z;
            acc[rr].w += yv.x * hv[0].w + yv.y * hv[1].w + yv.z * hv[2].w + yv.w * hv[3].w;
        }
    }
    #pragma unroll
    for (int rr = 0; rr < 4; rr++)
        *(float4*)&Om[(size_t)(r0 + 4 * rg + rr) * NN + 4 * cg] = acc[rr];
}

// ---------------------------------------------------------------------------
// Kernel B: per-pair serial recurrence -> U, V (rank 24)
// ---------------------------------------------------------------------------
__global__ void __launch_bounds__(384, 1)
k_recur(const float* __restrict__ steps, const float* __restrict__ dgs)
{
    extern __shared__ float smB[];
    float* Ys  = smB;                    // TT*NN
    float* Ss  = Ys  + TT * NN;
    float* G1s = Ss  + TT * NN;
    float* G2s = G1s + TT * NN;
    float* Us  = G2s + TT * NN;          // KK*NN (k-major)
    float* Vs  = Us  + KK * NN;

    __shared__ float wz[2 * KK];
    __shared__ float Hyv[NN], yHv[NN];
    __shared__ float red1[8], red2[8];
    __shared__ float csh[2];

    const int tid  = threadIdx.x;
    const int pair = blockIdx.x;
    const int lane = tid & 31;
    const int wid  = tid >> 5;
    const int half = tid / NN;           // 0 or 1
    const int li   = tid - half * NN;    // 0..191

    for (int idx = tid; idx < TT * NN; idx += 384) {
        const int t = idx / NN, n = idx - t * NN;
        const size_t g = (size_t)(t * NPAIRS + pair) * NN + n;
        Ys[idx]  = dgs[g];
        Ss[idx]  = steps[g];
        G1s[idx] = g_G1[g];
        G2s[idx] = g_G2[g];
    }
    __syncthreads();

    for (int t = 0; t < TT; t++) {
        const int k0 = 2 * t;
        const int ndots = 2 * k0;
        // wz[d<k0] = V_d . y_t ; wz[k0+k] = U_k . y_t
        for (int d = wid; d < ndots; d += 12) {
            const int k = (d < k0) ? d : (d - k0);
            const float* base = (d < k0) ? (Vs + k * NN) : (Us + k * NN);
            float p = 0.f;
            #pragma unroll
            for (int m = 0; m < NN / 32; m++)
                p += base[lane + 32 * m] * Ys[t * NN + lane + 32 * m];
            #pragma unroll
            for (int off = 16; off; off >>= 1)
                p += __shfl_down_sync(0xffffffffu, p, off);
            if (lane == 0) wz[d] = p;
        }
        __syncthreads();

        if (half == 0) {
            float hy = G1s[t * NN + li];
            for (int k = 0; k < k0; k++) hy += wz[k] * Us[k * NN + li];
            Hyv[li] = hy;
        } else {
            float yh = G2s[t * NN + li];
            for (int k = 0; k < k0; k++) yh += wz[k0 + k] * Vs[k * NN + li];
            yHv[li] = yh;
        }
        __syncthreads();

        if (half == 0) {
            const float sv = Ss[t * NN + li], yv = Ys[t * NN + li];
            float v1 = sv * yv;
            float v2 = yv * Hyv[li];
            #pragma unroll
            for (int off = 16; off; off >>= 1) {
                v1 += __shfl_down_sync(0xffffffffu, v1, off);
                v2 += __shfl_down_sync(0xffffffffu, v2, off);
            }
            if (lane == 0) { red1[wid] = v1; red2[wid] = v2; }
        }
        __syncthreads();
        if (tid == 0) {
            float sdot = 0.f, yHy = 0.f;
            #pragma unroll
            for (int w = 0; w < 6; w++) { sdot += red1[w]; yHy += red2[w]; }
            float c1, c2;
            if (sdot != 0.f) { c2 = 1.f / sdot; c1 = (sdot + yHy) * c2 * c2; }
            else             { c1 = 0.f; c2 = 0.f; }
            csh[0] = c1; csh[1] = c2;
        }
        __syncthreads();

        if (half == 0) {
            const float c1 = csh[0], c2 = csh[1];
            const float sv = Ss[t * NN + li];
            Us[(k0    ) * NN + li] = sv;
            Vs[(k0    ) * NN + li] = c1 * sv - c2 * yHv[li];
            Us[(k0 + 1) * NN + li] = -c2 * Hyv[li];
            Vs[(k0 + 1) * NN + li] = sv;
        }
        __syncthreads();
    }

    float* gu = g_U + (size_t)pair * KK * NN;
    float* gv = g_V + (size_t)pair * KK * NN;
    for (int idx = tid; idx < KK * NN; idx += 384) {
        gu[idx] = Us[idx];
        gv[idx] = Vs[idx];
    }
}

// ---------------------------------------------------------------------------
// Kernel C: out[pair][i][j] = H0[i][j] + sum_k U[pair][k][i] * V[pair][k][j]
// CTA: one pair, 32 i-rows x 192 cols, 384 threads, 4x4 tiles.
// ---------------------------------------------------------------------------
__global__ void __launch_bounds__(384)
k_expand(const float* __restrict__ H0, float* __restrict__ out)
{
    __shared__ float Vsh[KK][NN];        // [k][j]
    __shared__ float UshT[32][28];       // [i_local][k]
    const int tid  = threadIdx.x;
    const int pair = blockIdx.y;
    const int r0   = blockIdx.x * 32;

    const float* gv = g_V + (size_t)pair * KK * NN;
    const float* gu = g_U + (size_t)pair * KK * NN;
    for (int idx = tid; idx < KK * NN; idx += 384)
        ((float*)Vsh)[idx] = gv[idx];
    for (int idx = tid; idx < KK * 32; idx += 384) {
        const int k = idx >> 5, i = idx & 31;
        UshT[i][k] = gu[k * NN + r0 + i];
    }
    __syncthreads();

    const int cg = tid % 48;             // cols 4*cg..+3
    const int rg = tid / 48;             // rows r0+4*rg..+3
    float4 acc[4];
    #pragma unroll
    for (int rr = 0; rr < 4; rr++)
        acc[rr] = *(const float4*)&H0[(size_t)(r0 + 4 * rg + rr) * NN + 4 * cg];

    #pragma unroll
    for (int k4 = 0; k4 < KK / 4; k4++) {
        float4 vv[4];
        #pragma unroll
        for (int kk = 0; kk < 4; kk++)
            vv[kk] = *(const float4*)&Vsh[4 * k4 + kk][4 * cg];
        #pragma unroll
        for (int rr = 0; rr < 4; rr++) {
            const float4 uv = *(const float4*)&UshT[4 * rg + rr][4 * k4];
            acc[rr].x += uv.x * vv[0].x + uv.y * vv[1].x + uv.z * vv[2].x + uv.w * vv[3].x;
            acc[rr].y += uv.x * vv[0].y + uv.y * vv[1].y + uv.z * vv[2].y + uv.w * vv[3].y;
            acc[rr].z += uv.x * vv[0].z + uv.y * vv[1].z + uv.z * vv[2].z + uv.w * vv[3].z;
            acc[rr].w += uv.x * vv[0].w + uv.y * vv[1].w + uv.z * vv[2].w + uv.w * vv[3].w;
        }
    }
    float* op = out + (size_t)pair * NN * NN;
    #pragma unroll
    for (int rr = 0; rr < 4; rr++)
        *(float4*)&op[(size_t)(r0 + 4 * rg + rr) * NN + 4 * cg] = acc[rr];
}

// ---------------------------------------------------------------------------
extern "C" void kernel_launch(void* const* d_in, const int* in_sizes, int n_in,
                              void* d_out, int out_size)
{
    const float* H0    = (const float*)d_in[0];   // [N,N]
    const float* steps = (const float*)d_in[1];   // [T,B,E,N]
    const float* dgs   = (const float*)d_in[2];   // [T,B,E,N]
    float* out = (float*)d_out;                   // [B,E,N,N]

    const int smB_bytes = (4 * TT * NN + 2 * KK * NN) * sizeof(float);  // 73728
    cudaFuncSetAttribute(k_recur, cudaFuncAttributeMaxDynamicSharedMemorySize,
                         smB_bytes);

    k_transpose<<<36, dim3(32, 8)>>>(H0);
    k_gemm<<<dim3(NROWS / 32, 2), 384>>>(dgs, H0);
    k_recur<<<NPAIRS, 384, smB_bytes>>>(steps, dgs);
    k_expand<<<dim3(NN / 32, NPAIRS), 384>>>(H0, out);
}

// round 6
// speedup vs baseline: 1.1911x; 1.1911x over previous
#include <cuda_runtime.h>

#define TT 12
#define NN 192
#define KK 24                       // final rank = 2*TT
#define NPAIRS 256
#define NROWS (TT * NPAIRS)         // 3072
#define KP 28                       // UT/VT row pitch (112B, 16B-aligned)

// device scratch (static __device__ arrays are allowed; no dynamic allocs)
__device__ float g_H0T[NN * NN];
__device__ float g_G1[NROWS * NN];
__device__ float g_G2[NROWS * NN];
__device__ float g_U[NPAIRS * KK * NN];
__device__ float g_V[NPAIRS * KK * NN];

// ---------------------------------------------------------------------------
// Kernel 0: H0T = H0^T (tiled transpose)
// ---------------------------------------------------------------------------
__global__ void k_transpose(const float* __restrict__ H0)
{
    __shared__ float tbuf[32][33];
    const int bx = blockIdx.x % 6, by = blockIdx.x / 6;
    const int tx = threadIdx.x;
    for (int j = threadIdx.y; j < 32; j += 8)
        tbuf[j][tx] = H0[(by * 32 + j) * NN + bx * 32 + tx];
    __syncthreads();
    for (int j = threadIdx.y; j < 32; j += 8)
        g_H0T[(bx * 32 + j) * NN + by * 32 + tx] = tbuf[tx][j];
}

// ---------------------------------------------------------------------------
// Kernel A: batched GEMV as GEMM.
//   blockIdx.y==0: G1[r][i] = sum_k Y[r][k] * H0T[k][i]
//   blockIdx.y==1: G2[r][j] = sum_k Y[r][k] * H0 [k][j]
// ---------------------------------------------------------------------------
__global__ void __launch_bounds__(384)
k_gemm(const float* __restrict__ Y, const float* __restrict__ H0)
{
    __shared__ float Ysh[32][196];
    const int tid = threadIdx.x;
    const int r0 = blockIdx.x * 32;
    const float* __restrict__ Bm = blockIdx.y ? H0 : (const float*)g_H0T;
    float* __restrict__ Om = blockIdx.y ? g_G2 : g_G1;

    for (int idx = tid; idx < 32 * NN; idx += 384) {
        const int r = idx / NN, n = idx - r * NN;
        Ysh[r][n] = Y[(size_t)(r0 + r) * NN + n];
    }
    __syncthreads();

    const int cg = tid % 48;
    const int rg = tid / 48;
    float4 acc[4];
    #pragma unroll
    for (int rr = 0; rr < 4; rr++) acc[rr] = make_float4(0.f, 0.f, 0.f, 0.f);

    #pragma unroll 2
    for (int k4 = 0; k4 < NN / 4; k4++) {
        float4 hv[4];
        #pragma unroll
        for (int kk = 0; kk < 4; kk++)
            hv[kk] = *(const float4*)&Bm[(4 * k4 + kk) * NN + 4 * cg];
        #pragma unroll
        for (int rr = 0; rr < 4; rr++) {
            const float4 yv = *(const float4*)&Ysh[4 * rg + rr][4 * k4];
            acc[rr].x += yv.x * hv[0].x + yv.y * hv[1].x + yv.z * hv[2].x + yv.w * hv[3].x;
            acc[rr].y += yv.x * hv[0].y + yv.y * hv[1].y + yv.z * hv[2].y + yv.w * hv[3].y;
            acc[rr].z += yv.x * hv[0].z + yv.y * hv[1].z + yv.z * hv[2].z + yv.w * hv[3].z;
            acc[rr].w += yv.x * hv[0].w + yv.y * hv[1].w + yv.z * hv[2].w + yv.w * hv[3].w;
        }
    }
    #pragma unroll
    for (int rr = 0; rr < 4; rr++)
        *(float4*)&Om[(size_t)(r0 + 4 * rg + rr) * NN + 4 * cg] = acc[rr];
}

// ---------------------------------------------------------------------------
// Kernel B: per-pair serial recurrence -> U, V (rank 24)
// ---------------------------------------------------------------------------
__global__ void __launch_bounds__(384, 1)
k_recur(const float* __restrict__ steps, const float* __restrict__ dgs)
{
    extern __shared__ float smB[];
    float* Ys  = smB;                    // TT*NN
    float* Ss  = Ys  + TT * NN;
    float* G1s = Ss  + TT * NN;
    float* G2s = G1s + TT * NN;
    float* Us  = G2s + TT * NN;          // KK*NN (k-major)
    float* Vs  = Us  + KK * NN;

    __shared__ float wz[2 * KK];
    __shared__ float Hyv[NN], yHv[NN];
    __shared__ float red1[8], red2[8];
    __shared__ float csh[2];

    const int tid  = threadIdx.x;
    const int pair = blockIdx.x;
    const int lane = tid & 31;
    const int wid  = tid >> 5;
    const int half = tid / NN;
    const int li   = tid - half * NN;

    for (int idx = tid; idx < TT * NN; idx += 384) {
        const int t = idx / NN, n = idx - t * NN;
        const size_t g = (size_t)(t * NPAIRS + pair) * NN + n;
        Ys[idx]  = dgs[g];
        Ss[idx]  = steps[g];
        G1s[idx] = g_G1[g];
        G2s[idx] = g_G2[g];
    }
    __syncthreads();

    for (int t = 0; t < TT; t++) {
        const int k0 = 2 * t;
        const int ndots = 2 * k0;
        for (int d = wid; d < ndots; d += 12) {
            const int k = (d < k0) ? d : (d - k0);
            const float* base = (d < k0) ? (Vs + k * NN) : (Us + k * NN);
            float p = 0.f;
            #pragma unroll
            for (int m = 0; m < NN / 32; m++)
                p += base[lane + 32 * m] * Ys[t * NN + lane + 32 * m];
            #pragma unroll
            for (int off = 16; off; off >>= 1)
                p += __shfl_down_sync(0xffffffffu, p, off);
            if (lane == 0) wz[d] = p;
        }
        __syncthreads();

        if (half == 0) {
            float hy = G1s[t * NN + li];
            for (int k = 0; k < k0; k++) hy += wz[k] * Us[k * NN + li];
            Hyv[li] = hy;
        } else {
            float yh = G2s[t * NN + li];
            for (int k = 0; k < k0; k++) yh += wz[k0 + k] * Vs[k * NN + li];
            yHv[li] = yh;
        }
        __syncthreads();

        if (half == 0) {
            const float sv = Ss[t * NN + li], yv = Ys[t * NN + li];
            float v1 = sv * yv;
            float v2 = yv * Hyv[li];
            #pragma unroll
            for (int off = 16; off; off >>= 1) {
                v1 += __shfl_down_sync(0xffffffffu, v1, off);
                v2 += __shfl_down_sync(0xffffffffu, v2, off);
            }
            if (lane == 0) { red1[wid] = v1; red2[wid] = v2; }
        }
        __syncthreads();
        if (tid == 0) {
            float sdot = 0.f, yHy = 0.f;
            #pragma unroll
            for (int w = 0; w < 6; w++) { sdot += red1[w]; yHy += red2[w]; }
            float c1, c2;
            if (sdot != 0.f) { c2 = 1.f / sdot; c1 = (sdot + yHy) * c2 * c2; }
            else             { c1 = 0.f; c2 = 0.f; }
            csh[0] = c1; csh[1] = c2;
        }
        __syncthreads();

        if (half == 0) {
            const float c1 = csh[0], c2 = csh[1];
            const float sv = Ss[t * NN + li];
            Us[(k0    ) * NN + li] = sv;
            Vs[(k0    ) * NN + li] = c1 * sv - c2 * yHv[li];
            Us[(k0 + 1) * NN + li] = -c2 * Hyv[li];
            Vs[(k0 + 1) * NN + li] = sv;
        }
        __syncthreads();
    }

    float* gu = g_U + (size_t)pair * KK * NN;
    float* gv = g_V + (size_t)pair * KK * NN;
    for (int idx = tid; idx < KK * NN; idx += 384) {
        gu[idx] = Us[idx];
        gv[idx] = Vs[idx];
    }
}

// ---------------------------------------------------------------------------
// Kernel C v2: out[pair][i][j] = H0[i][j] + sum_k U[pair][k][i] * V[pair][k][j]
// One CTA per pair. U,V transposed once to UT/VT[row][k] (pitch 28).
// Warp tile = 16 rows x 16 cols; lane = 4 rows (stride-4) x 2 cols (float2).
//   uv loads: 8-way lane dedup, distinct banks across rr4 -> ~1 phase
//   vv loads: 4-way dedup -> ~2 phases
//   per k4: 6 LDS.128 (~8 phases) vs 8 FMA cyc -> FMA-bound
// ---------------------------------------------------------------------------
__global__ void __launch_bounds__(384)
k_expand(const float* __restrict__ H0, float* __restrict__ out)
{
    __shared__ float UT[NN * KP];        // [row i][k]
    __shared__ float VT[NN * KP];        // [col j][k]
    const int tid  = threadIdx.x;
    const int pair = blockIdx.x;

    const float* gu = g_U + (size_t)pair * KK * NN;
    const float* gv = g_V + (size_t)pair * KK * NN;
    for (int idx = tid; idx < KK * NN; idx += 384) {
        const int k = idx / NN, i = idx - k * NN;
        UT[i * KP + k] = gu[idx];
        VT[i * KP + k] = gv[idx];
    }
    __syncthreads();

    const int wid  = tid >> 5;
    const int lane = tid & 31;
    const int rr4  = lane >> 3;          // 0..3
    const int cc8  = lane & 7;           // 0..7
    float* op = out + (size_t)pair * NN * NN;

    #pragma unroll 1
    for (int tile = wid; tile < 144; tile += 12) {
        const int R0 = (tile / 12) * 16;
        const int c0 = (tile % 12) * 16 + 2 * cc8;

        float2 acc[4];
        #pragma unroll
        for (int q = 0; q < 4; q++) {
            const int r = R0 + rr4 + 4 * q;
            acc[q] = *(const float2*)&H0[(size_t)r * NN + c0];
        }

        const float* vt0 = &VT[(c0    ) * KP];
        const float* vt1 = &VT[(c0 + 1) * KP];
        #pragma unroll
        for (int k4 = 0; k4 < KK / 4; k4++) {
            const float4 vv0 = *(const float4*)&vt0[4 * k4];
            const float4 vv1 = *(const float4*)&vt1[4 * k4];
            #pragma unroll
            for (int q = 0; q < 4; q++) {
                const int r = R0 + rr4 + 4 * q;
                const float4 uv = *(const float4*)&UT[r * KP + 4 * k4];
                acc[q].x += uv.x * vv0.x + uv.y * vv0.y + uv.z * vv0.z + uv.w * vv0.w;
                acc[q].y += uv.x * vv1.x + uv.y * vv1.y + uv.z * vv1.z + uv.w * vv1.w;
            }
        }

        #pragma unroll
        for (int q = 0; q < 4; q++) {
            const int r = R0 + rr4 + 4 * q;
            *(float2*)&op[(size_t)r * NN + c0] = acc[q];
        }
    }
}

// ---------------------------------------------------------------------------
extern "C" void kernel_launch(void* const* d_in, const int* in_sizes, int n_in,
                              void* d_out, int out_size)
{
    const float* H0    = (const float*)d_in[0];   // [N,N]
    const float* steps = (const float*)d_in[1];   // [T,B,E,N]
    const float* dgs   = (const float*)d_in[2];   // [T,B,E,N]
    float* out = (float*)d_out;                   // [B,E,N,N]

    const int smB_bytes = (4 * TT * NN + 2 * KK * NN) * sizeof(float);  // 73728
    cudaFuncSetAttribute(k_recur, cudaFuncAttributeMaxDynamicSharedMemorySize,
                         smB_bytes);

    k_transpose<<<36, dim3(32, 8)>>>(H0);
    k_gemm<<<dim3(NROWS / 32, 2), 384>>>(dgs, H0);
    k_recur<<<NPAIRS, 384, smB_bytes>>>(steps, dgs);
    k_expand<<<NPAIRS, 384>>>(H0, out);
}